// round 6
// baseline (speedup 1.0000x reference)
#include <cuda_runtime.h>
#include <cuda_bf16.h>

// SSM kernel: out[l*256 + i] = exp(l * A[i][i]) * B[i] * C[i] + D
// L = 262144, n = 256. Pure write-bandwidth problem once the per-element exp
// is replaced by a per-strip geometric recurrence.

#define NCH 256          // SSM_DIM
#define RPB 256          // rows (l values) per block
#define THREADS 256      // 64 float4-lanes * 4 sub-rows

__global__ __launch_bounds__(THREADS)
void ssm_kernel(const float* __restrict__ A,
                const float* __restrict__ B,
                const float* __restrict__ C,
                const float* __restrict__ D,
                float* __restrict__ out,
                int L)
{
    const int j  = threadIdx.x & 63;   // float4 lane: channels 4j..4j+3
    const int s  = threadIdx.x >> 6;   // sub-row 0..3
    const int ch = j * 4;

    const int l0 = blockIdx.x * RPB + s;
    if (l0 >= L) return;

    const float d = D[0];

    // Diagonal of A (stride 257 floats), fused B*C per channel.
    const float a0 = A[(ch + 0) * 257];
    const float a1 = A[(ch + 1) * 257];
    const float a2 = A[(ch + 2) * 257];
    const float a3 = A[(ch + 3) * 257];

    const float bc0 = B[ch + 0] * C[ch + 0];
    const float bc1 = B[ch + 1] * C[ch + 1];
    const float bc2 = B[ch + 2] * C[ch + 2];
    const float bc3 = B[ch + 3] * C[ch + 3];

    // Strip start values and per-4-row ratios. l0 <= 2^18 is exact in fp32,
    // matching the reference's float32 powers[:,None]*a_log product.
    const float fl0 = (float)l0;
    float v0 = expf(fl0 * a0) * bc0;
    float v1 = expf(fl0 * a1) * bc1;
    float v2 = expf(fl0 * a2) * bc2;
    float v3 = expf(fl0 * a3) * bc3;

    const float r0 = expf(4.0f * a0);
    const float r1 = expf(4.0f * a1);
    const float r2 = expf(4.0f * a2);
    const float r3 = expf(4.0f * a3);

    // float4 index: (l*256 + 4j)/4 = l*64 + j. Max index 16.7M < 2^31.
    float4* o = reinterpret_cast<float4*>(out) + (size_t)l0 * 64 + j;

    const int rows_left = L - l0;                 // rows this thread could touch
    const int iters = (rows_left + 3) >> 2;       // step 4 rows per iter
    const int full  = (iters < RPB / 4) ? iters : RPB / 4;

#pragma unroll 4
    for (int it = 0; it < full; ++it) {
        float4 val;
        val.x = v0 + d;
        val.y = v1 + d;
        val.z = v2 + d;
        val.w = v3 + d;
        __stcs(o, val);            // streaming store; output never re-read
        v0 *= r0;
        v1 *= r1;
        v2 *= r2;
        v3 *= r3;
        o += 4 * 64;               // advance 4 rows
    }
}

extern "C" void kernel_launch(void* const* d_in, const int* in_sizes, int n_in,
                              void* d_out, int out_size)
{
    // Input order per metadata: [L (int32 scalar)], A(256x256), B(256), C(256), D(1).
    // Be defensive about whether the scalar L shows up as a device input.
    const int base = (n_in >= 5) ? 1 : 0;
    const float* A = (const float*)d_in[base + 0];
    const float* B = (const float*)d_in[base + 1];
    const float* C = (const float*)d_in[base + 2];
    const float* D = (const float*)d_in[base + 3];
    float* out = (float*)d_out;

    const int L = out_size / NCH;                 // out is (L, 256) fp32
    const int grid = (L + RPB - 1) / RPB;

    ssm_kernel<<<grid, THREADS>>>(A, B, C, D, out, L);
}

// round 7
// speedup vs baseline: 1.0700x; 1.0700x over previous
#include <cuda_runtime.h>
#include <cuda_bf16.h>

// SSM kernel: out[l*256 + i] = exp(l * A[i][i]) * B[i] * C[i] + D
// L = 262144, n = 256. Pure write-bandwidth problem once the per-element exp
// is replaced by a per-strip geometric recurrence with D folded in:
//   val_{l+4} = val_l * r + c,   r = exp(4*a),  c = d*(1-r)
// so the steady-state inner loop is 1 FFMA per channel + 1 STG.128 per 4 channels.

#define NCH 256          // SSM_DIM
#define RPB 128          // rows (l values) per block -> grid = 2048 (8 resident/SM + steal)
#define THREADS 256      // 64 float4-lanes * 4 sub-rows

__global__ __launch_bounds__(THREADS)
void ssm_kernel(const float* __restrict__ A,
                const float* __restrict__ B,
                const float* __restrict__ C,
                const float* __restrict__ D,
                float* __restrict__ out,
                int L)
{
    const int j  = threadIdx.x & 63;   // float4 lane: channels 4j..4j+3
    const int s  = threadIdx.x >> 6;   // sub-row 0..3
    const int ch = j * 4;

    const int l0 = blockIdx.x * RPB + s;
    if (l0 >= L) return;

    const float d = D[0];

    // Diagonal of A (stride 257 floats), fused B*C per channel.
    const float a0 = A[(ch + 0) * 257];
    const float a1 = A[(ch + 1) * 257];
    const float a2 = A[(ch + 2) * 257];
    const float a3 = A[(ch + 3) * 257];

    const float bc0 = B[ch + 0] * C[ch + 0];
    const float bc1 = B[ch + 1] * C[ch + 1];
    const float bc2 = B[ch + 2] * C[ch + 2];
    const float bc3 = B[ch + 3] * C[ch + 3];

    // Per-4-row ratios and the D-folding constant c = d*(1-r) = fma(-r, d, d).
    const float r0 = expf(4.0f * a0);
    const float r1 = expf(4.0f * a1);
    const float r2 = expf(4.0f * a2);
    const float r3 = expf(4.0f * a3);

    const float c0 = fmaf(-r0, d, d);
    const float c1 = fmaf(-r1, d, d);
    const float c2 = fmaf(-r2, d, d);
    const float c3 = fmaf(-r3, d, d);

    // Strip start values WITH d folded in: val = exp(l0*a)*bc + d.
    // l0 <= 2^18 is exact in fp32, matching the reference's fp32 product.
    const float fl0 = (float)l0;
    float v0 = fmaf(expf(fl0 * a0), bc0, d);
    float v1 = fmaf(expf(fl0 * a1), bc1, d);
    float v2 = fmaf(expf(fl0 * a2), bc2, d);
    float v3 = fmaf(expf(fl0 * a3), bc3, d);

    // float4 index: (l*256 + 4j)/4 = l*64 + j. Max index 16.7M < 2^31.
    float4* o = reinterpret_cast<float4*>(out) + (size_t)l0 * 64 + j;

    const int rows_left = L - l0;                 // rows this thread could touch
    const int iters = (rows_left + 3) >> 2;       // step 4 rows per iter
    const int full  = (iters < RPB / 4) ? iters : RPB / 4;   // RPB/4 = 32

#pragma unroll 8
    for (int it = 0; it < full; ++it) {
        float4 val;
        val.x = v0;
        val.y = v1;
        val.z = v2;
        val.w = v3;
        __stcs(o, val);            // streaming store; output never re-read
        v0 = fmaf(v0, r0, c0);     // val' = val*r + d*(1-r)
        v1 = fmaf(v1, r1, c1);
        v2 = fmaf(v2, r2, c2);
        v3 = fmaf(v3, r3, c3);
        o += 4 * 64;               // advance 4 rows
    }
}

extern "C" void kernel_launch(void* const* d_in, const int* in_sizes, int n_in,
                              void* d_out, int out_size)
{
    // Input order per metadata: [L (int32 scalar)], A(256x256), B(256), C(256), D(1).
    // Be defensive about whether the scalar L shows up as a device input.
    const int base = (n_in >= 5) ? 1 : 0;
    const float* A = (const float*)d_in[base + 0];
    const float* B = (const float*)d_in[base + 1];
    const float* C = (const float*)d_in[base + 2];
    const float* D = (const float*)d_in[base + 3];
    float* out = (float*)d_out;

    const int L = out_size / NCH;                 // out is (L, 256) fp32
    const int grid = (L + RPB - 1) / RPB;         // 2048 for L = 262144

    ssm_kernel<<<grid, THREADS>>>(A, B, C, D, out, L);
}